// round 15
// baseline (speedup 1.0000x reference)
#include <cuda_runtime.h>
#include <math.h>

#define B_  32
#define NP_ 2048
#define NG_ 2048
#define L_  256
#define BIGF 1e18f
#define EPSF 1e-6f

#define LAMBDA_E_SUM       10.0f
#define LAMBDA_HIT         20.0f
#define LAMBDA_CHAMFER     0.001f
#define LAMBDA_HIT_ENTROPY 0.1f

typedef unsigned long long ull;

// ---------------- device scratch ----------------
__device__ float4 g_predS[B_ * NP_];       // {-2x,-2y,-2z, pn}
__device__ float4 g_tgtS [B_ * NP_];       // {  x,  y,  z, tn}
// Global minima via atomicMin on order-preserving encoded uints.
// g_min1 values carry the target index in low 11 mantissa bits.
__device__ unsigned g_min1[B_ * NP_];
__device__ unsigned g_min2[B_ * NP_];
// g_acc: 0 sum minD_pred  1 sum|dE|  2 sum minD_tgt*mask
__device__ float g_acc[4];
// per-(batch,seg) partials, race-free slots: [b*4+seg][nhp,teh,nht,ent,kld]
__device__ float g_bat[128][8];
__device__ unsigned g_ticket;

// ---------------------------------------------------------------------------
__device__ __forceinline__ ull fma2(ull a, ull b, ull c) {
    ull d;
    asm("fma.rn.f32x2 %0, %1, %2, %3;" : "=l"(d) : "l"(a), "l"(b), "l"(c));
    return d;
}
__device__ __forceinline__ ull dup2(float x) {
    ull d;
    asm("mov.b64 %0, {%1, %1};" : "=l"(d) : "f"(x));
    return d;
}
__device__ __forceinline__ ull pk2(float a, float b) {
    ull d;
    asm("mov.b64 %0, {%1, %2};" : "=l"(d) : "f"(a), "f"(b));
    return d;
}
__device__ __forceinline__ float2 unpack2(ull v) {
    float2 r;
    asm("mov.b64 {%0, %1}, %2;" : "=f"(r.x), "=f"(r.y) : "l"(v));
    return r;
}
__device__ __forceinline__ unsigned encodeF(float f) {
    unsigned u = __float_as_uint(f);
    return u ^ ((unsigned)((int)u >> 31) | 0x80000000u);
}
__device__ __forceinline__ float decodeF(unsigned key, unsigned& raw) {
    unsigned m = (key & 0x80000000u) ? 0x80000000u : 0xFFFFFFFFu;
    raw = key ^ m;
    return __uint_as_float(raw);
}

__device__ __forceinline__ float blockReduceSum(float v, float* sh) {
    const unsigned full = 0xffffffffu;
    #pragma unroll
    for (int o = 16; o > 0; o >>= 1) v += __shfl_down_sync(full, v, o);
    int w = threadIdx.x >> 5, l = threadIdx.x & 31;
    __syncthreads();
    if (l == 0) sh[w] = v;
    __syncthreads();
    if (threadIdx.x < 32) {
        v = (threadIdx.x < (blockDim.x >> 5)) ? sh[threadIdx.x] : 0.0f;
        #pragma unroll
        for (int o = 16; o > 0; o >>= 1) v += __shfl_down_sync(full, v, o);
    }
    return v;
}

// ---------------------------------------------------------------------------
// 256 blocks: [0,128) pred-side (+kld), [128,256) target-side. 1 pair/thread.
// Writes only the scalar layouts; packed shared tiles are built in chamfer.
__global__ __launch_bounds__(256) void prep_kernel(
    const float* __restrict__ preds, const float* __restrict__ target,
    const float* __restrict__ mask,  const float* __restrict__ mu,
    const float* __restrict__ logvar) {
    __shared__ float shr[8];
    int blk = blockIdx.x, tid = threadIdx.x;

    // init: 65536 threads, one entry in each min array
    int gid = blk * 256 + tid;
    g_min1[gid] = 0xFFFFFFFFu;
    g_min2[gid] = 0xFFFFFFFFu;
    if (blk == 0 && tid < 4) g_acc[tid] = 0.0f;
    if (blk == 0 && tid == 4) g_ticket = 0u;

    if (blk < 128) {
        int b = blk >> 2, seg = blk & 3;
        int n = seg * 512 + 2 * tid;
        const float* pb = preds + (size_t)b * 5 * NP_;

        float2 x = *(const float2*)(pb + n);
        float2 y = *(const float2*)(pb + NP_ + n);
        float2 z = *(const float2*)(pb + 2 * NP_ + n);
        float2 E = *(const float2*)(pb + 3 * NP_ + n);
        float2 h = *(const float2*)(pb + 4 * NP_ + n);
        float pn0 = x.x * x.x + y.x * y.x + z.x * z.x;
        float pn1 = x.y * x.y + y.y * y.y + z.y * z.y;
        g_predS[b * NP_ + n]     = make_float4(-2.f * x.x, -2.f * y.x, -2.f * z.x, pn0);
        g_predS[b * NP_ + n + 1] = make_float4(-2.f * x.y, -2.f * y.y, -2.f * z.y, pn1);
        float nhp = h.x + h.y;
        float teh = E.x * h.x + E.y * h.y;
        float ent = -(h.x * __logf(h.x + EPSF) + (1.f - h.x) * __logf(1.f - h.x + EPSF))
                    -(h.y * __logf(h.y + EPSF) + (1.f - h.y) * __logf(1.f - h.y + EPSF));
        float kld = 0.f;
        if (seg == 0) {
            float m_ = mu[b * L_ + tid], lv = logvar[b * L_ + tid];
            kld = 1.f + lv - m_ * m_ - __expf(lv);
        }
        nhp = blockReduceSum(nhp, shr);
        teh = blockReduceSum(teh, shr);
        ent = blockReduceSum(ent, shr);
        kld = blockReduceSum(kld, shr);
        if (tid == 0) {
            float* s = g_bat[b * 4 + seg];
            s[0] = nhp; s[1] = teh; s[3] = ent; s[4] = kld;
        }
    } else {
        int w = blk - 128;
        int b = w >> 2, seg = w & 3;
        int n = seg * 512 + 2 * tid;
        const float* tb = target + (size_t)b * 4 * NG_;
        float2 x = *(const float2*)(tb + n);
        float2 y = *(const float2*)(tb + NG_ + n);
        float2 z = *(const float2*)(tb + 2 * NG_ + n);
        float2 mk = *(const float2*)(mask + b * NG_ + n);
        float tn0 = x.x * x.x + y.x * y.x + z.x * z.x;
        float tn1 = x.y * x.y + y.y * y.y + z.y * z.y;
        g_tgtS[b * NG_ + n]     = make_float4(x.x, y.x, z.x, tn0);
        g_tgtS[b * NG_ + n + 1] = make_float4(x.y, y.y, z.y, tn1);
        float nht = blockReduceSum(mk.x + mk.y, shr);
        if (tid == 0) g_bat[b * 4 + seg][2] = nht;
    }
}

// ---------------------------------------------------------------------------
// Chamfer: 4 pts/thread, occupancy 4, 2048 blocks, pass types INTERLEAVED:
//   blk even -> pass1 (pred->tgt, argmin in low 11 mantissa bits)
//   blk odd  -> pass2 (tgt->pred, plain min)
// u = blk>>1: b=u>>5, tile=(u>>4)&1, chunk=u&15. 64-thread fill builds the
// packed-pair shared layout directly from scalar arrays (+mask for pass1).
__global__ __launch_bounds__(256, 4) void chamfer_kernel(
    const float* __restrict__ mask) {
    __shared__ ulonglong2 shA[64], shB[64];
    int blk = blockIdx.x, tid = threadIdx.x;
    bool isP1 = (blk & 1) == 0;
    int u = blk >> 1;
    int b = u >> 5;
    int tile = (u >> 4) & 1;
    int chunk = u & 15;

    if (tid < 64) {
        int base = b * NP_ + chunk * 128 + 2 * tid;
        if (isP1) {
            float4 s0 = g_tgtS[base], s1 = g_tgtS[base + 1];
            float2 mk = *(const float2*)(mask + base);
            float w0 = s0.w + (mk.x == 0.f ? BIGF : 0.f);
            float w1 = s1.w + (mk.y == 0.f ? BIGF : 0.f);
            shA[tid] = make_ulonglong2(pk2(s0.x, s1.x), pk2(s0.y, s1.y));
            shB[tid] = make_ulonglong2(pk2(s0.z, s1.z), pk2(w0, w1));
        } else {
            float4 s0 = g_predS[base], s1 = g_predS[base + 1];
            shA[tid] = make_ulonglong2(pk2(s0.x, s1.x), pk2(s0.y, s1.y));
            shB[tid] = make_ulonglong2(pk2(s0.z, s1.z), pk2(s0.w, s1.w));
        }
    }
    __syncthreads();

    if (isP1) {
        int pbase = b * NP_ + tile * 1024 + tid;
        ull ax2[4], ay2[4], az2[4];
        #pragma unroll
        for (int i = 0; i < 4; i++) {
            float4 p = g_predS[pbase + i * 256];
            ax2[i] = dup2(p.x); ay2[i] = dup2(p.y); az2[i] = dup2(p.z);
        }
        float bl[4], bh[4];
        #pragma unroll
        for (int i = 0; i < 4; i++) { bl[i] = 3.4e38f; bh[i] = 3.4e38f; }

        unsigned jlo = (unsigned)(chunk * 128);
        #pragma unroll 4
        for (int j = 0; j < 64; j++) {
            ulonglong2 A = shA[j], Bv = shB[j];
            unsigned jhi = jlo | 1u;
            #pragma unroll
            for (int i = 0; i < 4; i++) {
                ull t = fma2(az2[i], Bv.x, Bv.y);
                t = fma2(ay2[i], A.y, t);
                t = fma2(ax2[i], A.x, t);
                float2 v = unpack2(t);
                unsigned elo = (__float_as_uint(v.x) & 0xFFFFF800u) | jlo;
                unsigned ehi = (__float_as_uint(v.y) & 0xFFFFF800u) | jhi;
                bl[i] = fminf(bl[i], __uint_as_float(elo));
                bh[i] = fminf(bh[i], __uint_as_float(ehi));
            }
            jlo += 2;
        }
        #pragma unroll
        for (int i = 0; i < 4; i++)
            atomicMin(&g_min1[pbase + i * 256], encodeF(fminf(bl[i], bh[i])));
    } else {
        int tbase = b * NG_ + tile * 1024 + tid;
        ull tx2[4], ty2[4], tz2[4];
        #pragma unroll
        for (int i = 0; i < 4; i++) {
            float4 t = g_tgtS[tbase + i * 256];
            tx2[i] = dup2(t.x); ty2[i] = dup2(t.y); tz2[i] = dup2(t.z);
        }
        float bl[4], bh[4];
        #pragma unroll
        for (int i = 0; i < 4; i++) { bl[i] = 3.4e38f; bh[i] = 3.4e38f; }

        #pragma unroll 4
        for (int j = 0; j < 64; j++) {
            ulonglong2 A = shA[j], Bv = shB[j];
            #pragma unroll
            for (int i = 0; i < 4; i++) {
                ull t = fma2(tz2[i], Bv.x, Bv.y);
                t = fma2(ty2[i], A.y, t);
                t = fma2(tx2[i], A.x, t);
                float2 v = unpack2(t);
                bl[i] = fminf(bl[i], v.x);
                bh[i] = fminf(bh[i], v.y);
            }
        }
        #pragma unroll
        for (int i = 0; i < 4; i++)
            atomicMin(&g_min2[tbase + i * 256], encodeF(fminf(bl[i], bh[i])));
    }
}

// ---------------------------------------------------------------------------
// Combine + final. 512 blocks, 256 points each (1/thread):
//   [0,256)  pred side: minD_pred, |dE|
//   [256,512) tgt side: minD_tgt*mask
// Last block (ticket) computes the scalar losses.
__global__ __launch_bounds__(256) void combine_kernel(
    const float* __restrict__ preds, const float* __restrict__ target,
    const float* __restrict__ mask,  const float* __restrict__ e_init,
    const float* __restrict__ kl_weight, float* __restrict__ out, int out_size) {
    __shared__ float shr[8];
    __shared__ int s_last;
    int blk = blockIdx.x, tid = threadIdx.x;

    if (blk < 256) {
        int n = blk * 256 + tid;
        unsigned raw;
        float best = decodeF(g_min1[n], raw);
        int idx = (int)(raw & 0x7FFu);
        int b = n >> 11, nn = n & (NP_ - 1);
        float md = fmaxf(g_predS[n].w + best, 0.f);
        float tE = target[(size_t)b * 4 * NG_ + 3 * NG_ + idx];
        float pE = preds[(size_t)b * 5 * NP_ + 3 * NP_ + nn];
        float le = fabsf(pE - tE);
        md = blockReduceSum(md, shr);
        le = blockReduceSum(le, shr);
        if (tid == 0) { atomicAdd(&g_acc[0], md); atomicAdd(&g_acc[1], le); }
    } else {
        int m = (blk - 256) * 256 + tid;
        unsigned raw;
        float best = decodeF(g_min2[m], raw);
        float s = fmaxf(g_tgtS[m].w + best, 0.f) * mask[m];
        s = blockReduceSum(s, shr);
        if (tid == 0) atomicAdd(&g_acc[2], s);
    }

    if (tid == 0) {
        __threadfence();
        unsigned t = atomicAdd(&g_ticket, 1u);
        s_last = (t == 511u);
    }
    __syncthreads();
    if (!s_last) return;

    int t = tid;
    float dh2 = 0.f, de2 = 0.f, ent = 0.f, kld = 0.f, nhtTot = 0.f;
    if (t < B_) {
        float nhp = 0.f, teh = 0.f, nht = 0.f;
        #pragma unroll
        for (int s2 = 0; s2 < 4; s2++) {
            const float* sb = g_bat[t * 4 + s2];
            nhp += sb[0]; teh += sb[1]; nht += sb[2];
            ent += sb[3]; kld += sb[4];
        }
        float dh = nhp - nht;
        float de = teh - e_init[t];
        dh2 = dh * dh; de2 = de * de; nhtTot = nht;
    }
    if (t < 32) {
        const unsigned full = 0xffffffffu;
        #pragma unroll
        for (int o = 16; o > 0; o >>= 1) {
            dh2 += __shfl_down_sync(full, dh2, o);
            de2 += __shfl_down_sync(full, de2, o);
            ent += __shfl_down_sync(full, ent, o);
            kld += __shfl_down_sync(full, kld, o);
            nhtTot += __shfl_down_sync(full, nhtTot, o);
        }
        if (t == 0) {
            float a0 = atomicAdd(&g_acc[0], 0.f);
            float a1 = atomicAdd(&g_acc[1], 0.f);
            float a2 = atomicAdd(&g_acc[2], 0.f);
            float chamP = a0 / (float)(B_ * NP_);
            float chamT = a2 / nhtTot;
            float loss_chamf = (chamT + chamP) * LAMBDA_CHAMFER;
            float localE = a1 / (float)(B_ * NP_);
            float ge   = LAMBDA_E_SUM * de2 / (float)B_;
            float hit  = LAMBDA_HIT   * dh2 / (float)B_;
            float entr = LAMBDA_HIT_ENTROPY * ent / (float)(B_ * NP_);
            float kl   = kl_weight[0] * (-0.5f * kld / (float)B_);
            float total = loss_chamf + localE + kl + ge + hit + entr;

            if (out_size >= 6) {
                out[0] = total;
                out[1] = loss_chamf;
                out[2] = localE;
                out[3] = ge;
                out[4] = hit;
                out[5] = kl;
            } else if (out_size == 5) {
                out[0] = loss_chamf; out[1] = localE; out[2] = ge;
                out[3] = hit;        out[4] = kl;
            } else {
                out[0] = total;
            }
        }
    }
}

// ---------------------------------------------------------------------------
extern "C" void kernel_launch(void* const* d_in, const int* in_sizes, int n_in,
                              void* d_out, int out_size) {
    const float* preds  = (const float*)d_in[0];
    const float* target = (const float*)d_in[1];
    const float* tmask  = (const float*)d_in[2];
    const float* mu     = (const float*)d_in[3];
    const float* logvar = (const float*)d_in[4];
    const float* e_init = (const float*)d_in[5];
    const float* klw    = (const float*)d_in[6];
    float* out = (float*)d_out;

    prep_kernel<<<256, 256>>>(preds, target, tmask, mu, logvar);
    chamfer_kernel<<<2048, 256>>>(tmask);
    combine_kernel<<<512, 256>>>(preds, target, tmask, e_init, klw, out, out_size);
}